// round 6
// baseline (speedup 1.0000x reference)
#include <cuda_runtime.h>

// MultiScaleMovingAvg via per-thread running box sums.
// R6: half-block restructured as [bulk LDS staging rows -> issue next groups
// -> compute (all-register) -> wait]. Issuing BEFORE compute gives each
// cp.async group ~2 compute phases of latency budget (vs 1 in R5), with the
// same 32-row ring (16KB/CTA, single wave). Max pending span = 32 rows, so
// every ring slot has exactly one pending writer (no async-write aliasing).

#define B_DIM 16
#define S_DIM 4096
#define F_DIM 512
#define SEG   256
#define TPB   128
#define RING  32          // rows per warp ring (power of 2)

__device__ __forceinline__ void cp_async16(unsigned saddr, const void* gptr) {
    asm volatile("cp.async.cg.shared.global [%0], [%1], 16;\n"
                 :: "r"(saddr), "l"(gptr));
}
__device__ __forceinline__ void cp_commit() {
    asm volatile("cp.async.commit_group;\n");
}
template <int N>
__device__ __forceinline__ void cp_wait() {
    asm volatile("cp.async.wait_group %0;\n" :: "n"(N));
}

__global__ void __launch_bounds__(TPB)
msma_kernel(const float* __restrict__ x,
            const float* __restrict__ kw,
            float* __restrict__ out) {
    __shared__ float ring[4][RING][32];   // 16 KB

    const int lane = threadIdx.x & 31;
    const int warp = threadIdx.x >> 5;
    const int f0   = blockIdx.x * TPB + warp * 32;  // 32 channels per warp
    const int s0   = blockIdx.y * SEG;              // multiple of 256
    const int b    = blockIdx.z;

    // softmax over the 4 kernel weights, folded with 1/k
    const float k0 = kw[0], k1 = kw[1], k2 = kw[2], k3 = kw[3];
    const float mx = fmaxf(fmaxf(k0, k1), fmaxf(k2, k3));
    const float e0 = __expf(k0 - mx), e1 = __expf(k1 - mx);
    const float e2 = __expf(k2 - mx), e3 = __expf(k3 - mx);
    const float inv = 1.0f / (e0 + e1 + e2 + e3);
    const float c3  = e0 * inv * (1.0f / 3.0f);
    const float c7  = e1 * inv * (1.0f / 7.0f);
    const float c15 = e2 * inv * (1.0f / 15.0f);
    const float c31 = e3 * inv * (1.0f / 31.0f);

    const float* __restrict__ xb = x + (size_t)b * S_DIM * F_DIM;
    float (* __restrict__ rw)[32] = ring[warp];

    // producer mapping: one cp.async round of 8 lanes = one 128B row
    const int prow = lane >> 3;           // 0..3 (row within quad)
    const int pcol = (lane & 7) << 2;     // channel offset 0,4,..,28
    const unsigned rbase =
        (unsigned)__cvta_generic_to_shared(&ring[warp][0][0]);
    const unsigned pbyte = (unsigned)(pcol << 2);

    // issue one 8-row group [r, r+7]; slot keyed by LOGICAL row & 31,
    // data from row clamped to [0, S-1]  (replicate padding)
    auto issue_group = [&](int r) {
        int ra = r + prow, rb = r + 4 + prow;
        int ca = ra < 0 ? 0 : (ra > S_DIM - 1 ? S_DIM - 1 : ra);
        int cb = rb < 0 ? 0 : (rb > S_DIM - 1 ? S_DIM - 1 : rb);
        unsigned da = rbase + ((unsigned)(ra & (RING - 1)) << 7) + pbyte;
        unsigned db = rbase + ((unsigned)(rb & (RING - 1)) << 7) + pbyte;
        cp_async16(da, xb + (size_t)ca * F_DIM + f0 + pcol);
        cp_async16(db, xb + (size_t)cb * F_DIM + f0 + pcol);
        cp_commit();
    };

    // ---- Prologue phase 1: rows [s0-15, s0+16] fill the whole ring ----
    issue_group(s0 - 15); issue_group(s0 - 7);
    issue_group(s0 + 1);  issue_group(s0 + 9);
    cp_wait<0>();
    __syncwarp();

    // Q[row & 31] = x[row] for rows s0-15 .. s0+16  (s0 % 32 == 0)
    float Q[32];
    #pragma unroll
    for (int i = 0; i < 32; ++i) Q[i] = rw[i][lane];

    // initial window sums at s = s0 (slot of s0+t is t & 31)
    float W3 = Q[31] + Q[0] + Q[1];
    float W7 = W3;
    #pragma unroll
    for (int t = 2; t <= 3; ++t)  W7  += Q[t] + Q[32 - t];
    float W15 = W7;
    #pragma unroll
    for (int t = 4; t <= 7; ++t)  W15 += Q[t] + Q[32 - t];
    float W31 = W15;
    #pragma unroll
    for (int t = 8; t <= 15; ++t) W31 += Q[t] + Q[32 - t];

    __syncwarp();   // whole ring consumed into Q; all slots reusable

    // ---- Prologue phase 2: issue rows [s0+17, s0+48] (4 groups) ----
    issue_group(s0 + 17); issue_group(s0 + 25);
    issue_group(s0 + 33); issue_group(s0 + 41);
    cp_wait<2>();            // rows <= s0+32 complete; (s0+32, s0+48] pending
    __syncwarp();

    float* __restrict__ op = out + ((size_t)b * S_DIM + s0) * F_DIM + f0 + lane;

    // ---- Main loop ----
    // Invariant at top of half-block p: rows <= p+32 complete,
    // (p+32, p+48] pending (2 groups).
    #pragma unroll 1
    for (int ob = 0; ob < SEG / 32; ++ob) {
        #pragma unroll
        for (int h = 0; h < 2; ++h) {
            const int PAR   = h * 16;                // compile-time
            const int p_rel = ob * 32 + PAR;

            // 1) bulk-stage rows p+17..p+32 into registers (complete by invariant)
            float T[16];
            #pragma unroll
            for (int u = 0; u < 16; ++u)
                T[u] = rw[(PAR + 17 + u) & 31][lane];
            __syncwarp();    // slots of rows p+17..p+32 now reusable

            // 2) issue next 2 groups (rows p+49..p+64) BEFORE compute:
            //    each group now has ~2 compute phases before its wait.
            const bool iA = (p_rel + 49 <= SEG + 16);
            const bool iB = (p_rel + 57 <= SEG + 16);
            if (iA) issue_group(s0 + p_rel + 49);
            if (iB) issue_group(s0 + p_rel + 57);

            // 3) compute 16 steps, fully register-resident
            #pragma unroll
            for (int u = 0; u < 16; ++u) {
                const int sl = PAR + u;              // compile-time
                float o = c3 * W3;
                o = fmaf(c7,  W7,  o);
                o = fmaf(c15, W15, o);
                o = fmaf(c31, W31, o);
                op[(size_t)sl * F_DIM] = o;
                W3  += Q[(sl + 2)  & 31] - Q[(sl + 31) & 31]; // +x[s+2]  -x[s-1]
                W7  += Q[(sl + 4)  & 31] - Q[(sl + 29) & 31]; // +x[s+4]  -x[s-3]
                W15 += Q[(sl + 8)  & 31] - Q[(sl + 25) & 31]; // +x[s+8]  -x[s-7]
                W31 += Q[(sl + 16) & 31] - Q[(sl + 17) & 31]; // +x[s+16] -x[s-15]
                Q[(sl + 17) & 31] = T[u];                     // insert x[s+17]
            }

            // 4) wait so that next half-block has rows <= p+48 complete
            if (iA) {
                cp_wait<2>();                 // pending 4 -> 2
            } else if (p_rel == SEG - 32) {
                cp_wait<0>();                 // drain final groups (<= SEG+16)
            }
            __syncwarp();
        }
        op += (size_t)32 * F_DIM;
    }
}

extern "C" void kernel_launch(void* const* d_in, const int* in_sizes, int n_in,
                              void* d_out, int out_size) {
    const float* x  = (const float*)d_in[0];   // [16, 4096, 512] fp32
    const float* kw = (const float*)d_in[1];   // [4] fp32
    float* out = (float*)d_out;                // [16, 4096, 512] fp32

    dim3 grid(F_DIM / TPB, S_DIM / SEG, B_DIM); // (4, 16, 16) = 1024 blocks
    msma_kernel<<<grid, TPB>>>(x, kw, out);
}